// round 6
// baseline (speedup 1.0000x reference)
#include <cuda_runtime.h>

// DynamicUpsamplingFilter:
//   x:       (1, 3, 25, 128, 128) float32          -> d_in[0]
//   filters: (1, 25, 16, 25, 128, 128) float32     -> d_in[1]
//   out:     (1, 48, 25, 128, 128) float32
// out[c*16+u, t, h, w] = sum_{a,b} x[c, t, h+a-2, w+b-2] * filters[a*5+b, u, t, h, w]
//
// R6: one u per thread (4 u per block, grid.y = 4). 12 accumulator floats
// -> ~50 regs -> ~10 CTAs/SM (40 warps) for maximum DRAM latency hiding.
// float4 filter loads/stores, conflict-free float4 LDS windows.

#define T_DIM 25
#define H_DIM 128
#define W_DIM 128
#define HW    (H_DIM * W_DIM)       // 16384
#define THW   (T_DIM * HW)          // 409600
#define C_IN  3
#define KH    5
#define KW    5
#define UPSQ  16

__global__ __launch_bounds__(128, 10)
void duf_kernel(const float* __restrict__ x,
                const float* __restrict__ f,
                float* __restrict__ out)
{
    const int tid = threadIdx.x;
    const int w4  = tid & 31;            // float4 index over w
    const int ug  = tid >> 5;            // 0..3
    const int w0  = w4 << 2;
    const int h = blockIdx.x & (H_DIM - 1);
    const int t = blockIdx.x >> 7;
    const int u = blockIdx.y * 4 + ug;   // this thread's u

    // x patch tile: 3 channels x 5 rows x (128 + 4) cols, zero halo in w.
    __shared__ __align__(16) float sx[C_IN][KH][W_DIM + 4];

    if (tid < 2) {
        #pragma unroll
        for (int c = 0; c < C_IN; c++)
            #pragma unroll
            for (int a = 0; a < KH; a++) {
                sx[c][a][tid] = 0.0f;
                sx[c][a][W_DIM + 2 + tid] = 0.0f;
            }
    }

    // stage x rows h-2..h+2 for all 3 channels (tid = w index here)
    #pragma unroll
    for (int c = 0; c < C_IN; c++) {
        #pragma unroll
        for (int a = 0; a < KH; a++) {
            const int hh = h + a - 2;
            float v = 0.0f;
            if (hh >= 0 && hh < H_DIM)
                v = __ldg(&x[c * THW + t * HW + hh * W_DIM + tid]);
            sx[c][a][tid + 2] = v;
        }
    }
    __syncthreads();

    const int rowbase = t * HW + h * W_DIM;
    // filter pointer for (k=0, this u, this row, w0)
    const float4* fp = (const float4*)(f + (size_t)u * THW + rowbase + w0);

    float4 acc[C_IN];
    #pragma unroll
    for (int c = 0; c < C_IN; c++)
        acc[c] = make_float4(0.f, 0.f, 0.f, 0.f);

    #pragma unroll 1
    for (int a = 0; a < KH; a++) {
        // conflict-free window: 8 floats per channel as two aligned LDS.128
        float win[C_IN][8];
        #pragma unroll
        for (int c = 0; c < C_IN; c++) {
            const float4 lo = *(const float4*)&sx[c][a][w0];
            const float4 hi = *(const float4*)&sx[c][a][w0 + 4];
            win[c][0] = lo.x; win[c][1] = lo.y; win[c][2] = lo.z; win[c][3] = lo.w;
            win[c][4] = hi.x; win[c][5] = hi.y; win[c][6] = hi.z; win[c][7] = hi.w;
        }

        const float4* fa = fp + (size_t)(a * KW) * (UPSQ * THW / 4);

        // 5 independent streaming loads issued up front (b unrolled)
        float4 fv[KW];
        #pragma unroll
        for (int b = 0; b < KW; b++)
            fv[b] = __ldg(fa + (size_t)b * (UPSQ * THW / 4));

        #pragma unroll
        for (int b = 0; b < KW; b++) {
            #pragma unroll
            for (int c = 0; c < C_IN; c++) {
                acc[c].x = fmaf(win[c][b],     fv[b].x, acc[c].x);
                acc[c].y = fmaf(win[c][b + 1], fv[b].y, acc[c].y);
                acc[c].z = fmaf(win[c][b + 2], fv[b].z, acc[c].z);
                acc[c].w = fmaf(win[c][b + 3], fv[b].w, acc[c].w);
            }
        }
    }

    // out[(c*16 + u)*THW + rowbase + w0], 512B/warp stores
    float4* op = (float4*)(out + (size_t)u * THW + rowbase + w0);
    #pragma unroll
    for (int c = 0; c < C_IN; c++)
        op[(size_t)c * UPSQ * (THW / 4)] = acc[c];
}

extern "C" void kernel_launch(void* const* d_in, const int* in_sizes, int n_in,
                              void* d_out, int out_size)
{
    const float* x = (const float*)d_in[0];
    const float* f = (const float*)d_in[1];
    float* out = (float*)d_out;

    dim3 grid(T_DIM * H_DIM, 4);  // (t*h row, u quarter)
    dim3 block(128);
    duf_kernel<<<grid, block>>>(x, f, out);
}

// round 7
// speedup vs baseline: 1.0172x; 1.0172x over previous
#include <cuda_runtime.h>

// DynamicUpsamplingFilter:
//   x:       (1, 3, 25, 128, 128) float32          -> d_in[0]
//   filters: (1, 25, 16, 25, 128, 128) float32     -> d_in[1]
//   out:     (1, 48, 25, 128, 128) float32
// out[c*16+u, t, h, w] = sum_{a,b} x[c, t, h+a-2, w+b-2] * filters[a*5+b, u, t, h, w]
//
// R7: R5 (best: UG=2, 7 CTAs/SM = 28 warps, float4 LDG, conflict-free float4
// LDS windows) + streaming stores (__stcs) for the write stream.
// Kernel is at its DRAM traffic floor (~734 MB @ ~6.45 TB/s); this targets
// controller read/write turnaround efficiency only.

#define T_DIM 25
#define H_DIM 128
#define W_DIM 128
#define HW    (H_DIM * W_DIM)       // 16384
#define THW   (T_DIM * HW)          // 409600
#define C_IN  3
#define KH    5
#define KW    5
#define UPSQ  16
#define UG    2                     // u per thread

__global__ __launch_bounds__(128, 7)
void duf_kernel(const float* __restrict__ x,
                const float* __restrict__ f,
                float* __restrict__ out)
{
    const int tid = threadIdx.x;
    const int w4  = tid & 31;            // float4 index over w
    const int ug  = tid >> 5;            // 0..3
    const int w0  = w4 << 2;
    const int h = blockIdx.x & (H_DIM - 1);
    const int t = blockIdx.x >> 7;
    const int u0 = blockIdx.y * 8 + ug * UG;   // first u of this thread

    // x patch tile: 3 channels x 5 rows x (128 + 4) cols, zero halo in w.
    __shared__ __align__(16) float sx[C_IN][KH][W_DIM + 4];

    if (tid < 2) {
        #pragma unroll
        for (int c = 0; c < C_IN; c++)
            #pragma unroll
            for (int a = 0; a < KH; a++) {
                sx[c][a][tid] = 0.0f;
                sx[c][a][W_DIM + 2 + tid] = 0.0f;
            }
    }

    // stage x rows h-2..h+2 for all 3 channels (tid = w index here)
    #pragma unroll
    for (int c = 0; c < C_IN; c++) {
        #pragma unroll
        for (int a = 0; a < KH; a++) {
            const int hh = h + a - 2;
            float v = 0.0f;
            if (hh >= 0 && hh < H_DIM)
                v = __ldg(&x[c * THW + t * HW + hh * W_DIM + tid]);
            sx[c][a][tid + 2] = v;
        }
    }
    __syncthreads();

    const int rowbase = t * HW + h * W_DIM;
    // filter pointer for (k=0, u=u0, this row, w0)
    const float4* fp = (const float4*)(f + (size_t)u0 * THW + rowbase + w0);

    float4 acc[C_IN][UG];
    #pragma unroll
    for (int c = 0; c < C_IN; c++)
        #pragma unroll
        for (int j = 0; j < UG; j++)
            acc[c][j] = make_float4(0.f, 0.f, 0.f, 0.f);

    #pragma unroll 1
    for (int a = 0; a < KH; a++) {
        // conflict-free window: 8 floats per channel as two aligned LDS.128
        float win[C_IN][8];
        #pragma unroll
        for (int c = 0; c < C_IN; c++) {
            const float4 lo = *(const float4*)&sx[c][a][w0];
            const float4 hi = *(const float4*)&sx[c][a][w0 + 4];
            win[c][0] = lo.x; win[c][1] = lo.y; win[c][2] = lo.z; win[c][3] = lo.w;
            win[c][4] = hi.x; win[c][5] = hi.y; win[c][6] = hi.z; win[c][7] = hi.w;
        }

        const float4* fa = fp + (size_t)(a * KW) * (UPSQ * THW / 4);

        #pragma unroll
        for (int b = 0; b < KW; b++) {
            const float4* fk = fa + (size_t)b * (UPSQ * THW / 4);
            float4 fv[UG];
            #pragma unroll
            for (int j = 0; j < UG; j++)
                fv[j] = __ldg(fk + (size_t)j * (THW / 4));

            #pragma unroll
            for (int c = 0; c < C_IN; c++) {
                const float p0 = win[c][b];
                const float p1 = win[c][b + 1];
                const float p2 = win[c][b + 2];
                const float p3 = win[c][b + 3];
                #pragma unroll
                for (int j = 0; j < UG; j++) {
                    acc[c][j].x = fmaf(p0, fv[j].x, acc[c][j].x);
                    acc[c][j].y = fmaf(p1, fv[j].y, acc[c][j].y);
                    acc[c][j].z = fmaf(p2, fv[j].z, acc[c][j].z);
                    acc[c][j].w = fmaf(p3, fv[j].w, acc[c][j].w);
                }
            }
        }
    }

    // out[(c*16 + u0 + j)*THW + rowbase + w0], 512B/warp streaming stores
    float4* op = (float4*)(out + (size_t)u0 * THW + rowbase + w0);
    #pragma unroll
    for (int c = 0; c < C_IN; c++)
        #pragma unroll
        for (int j = 0; j < UG; j++)
            __stcs(&op[((size_t)c * UPSQ + j) * (THW / 4)], acc[c][j]);
}

extern "C" void kernel_launch(void* const* d_in, const int* in_sizes, int n_in,
                              void* d_out, int out_size)
{
    const float* x = (const float*)d_in[0];
    const float* f = (const float*)d_in[1];
    float* out = (float*)d_out;

    dim3 grid(T_DIM * H_DIM, 2);  // (t*h row, u-half)
    dim3 block(128);
    duf_kernel<<<grid, block>>>(x, f, out);
}

// round 8
// speedup vs baseline: 1.0339x; 1.0164x over previous
#include <cuda_runtime.h>

// DynamicUpsamplingFilter:
//   x:       (1, 3, 25, 128, 128) float32          -> d_in[0]
//   filters: (1, 25, 16, 25, 128, 128) float32     -> d_in[1]
//   out:     (1, 48, 25, 128, 128) float32
// out[c*16+u, t, h, w] = sum_{a,b} x[c, t, h+a-2, w+b-2] * filters[a*5+b, u, t, h, w]
//
// R8: R7 (UG=2, 7 CTAs/SM, float4 LDG, conflict-free LDS windows, __stcs)
// with the a-loop FULLY UNROLLED so ptxas can software-pipeline filter loads
// across iterations (sustained ~20+ outstanding LDG.128 per warp instead of
// bursty 10), closing the DRAM request-supply gaps (81% -> target 84-86%).

#define T_DIM 25
#define H_DIM 128
#define W_DIM 128
#define HW    (H_DIM * W_DIM)       // 16384
#define THW   (T_DIM * HW)          // 409600
#define C_IN  3
#define KH    5
#define KW    5
#define UPSQ  16
#define UG    2                     // u per thread

__global__ __launch_bounds__(128, 7)
void duf_kernel(const float* __restrict__ x,
                const float* __restrict__ f,
                float* __restrict__ out)
{
    const int tid = threadIdx.x;
    const int w4  = tid & 31;            // float4 index over w
    const int ug  = tid >> 5;            // 0..3
    const int w0  = w4 << 2;
    const int h = blockIdx.x & (H_DIM - 1);
    const int t = blockIdx.x >> 7;
    const int u0 = blockIdx.y * 8 + ug * UG;   // first u of this thread

    // x patch tile: 3 channels x 5 rows x (128 + 4) cols, zero halo in w.
    __shared__ __align__(16) float sx[C_IN][KH][W_DIM + 4];

    if (tid < 2) {
        #pragma unroll
        for (int c = 0; c < C_IN; c++)
            #pragma unroll
            for (int a = 0; a < KH; a++) {
                sx[c][a][tid] = 0.0f;
                sx[c][a][W_DIM + 2 + tid] = 0.0f;
            }
    }

    // stage x rows h-2..h+2 for all 3 channels (tid = w index here)
    #pragma unroll
    for (int c = 0; c < C_IN; c++) {
        #pragma unroll
        for (int a = 0; a < KH; a++) {
            const int hh = h + a - 2;
            float v = 0.0f;
            if (hh >= 0 && hh < H_DIM)
                v = __ldg(&x[c * THW + t * HW + hh * W_DIM + tid]);
            sx[c][a][tid + 2] = v;
        }
    }
    __syncthreads();

    const int rowbase = t * HW + h * W_DIM;
    // filter pointer for (k=0, u=u0, this row, w0)
    const float4* fp = (const float4*)(f + (size_t)u0 * THW + rowbase + w0);

    float4 acc[C_IN][UG];
    #pragma unroll
    for (int c = 0; c < C_IN; c++)
        #pragma unroll
        for (int j = 0; j < UG; j++)
            acc[c][j] = make_float4(0.f, 0.f, 0.f, 0.f);

    // FULL unroll: lets ptxas pipeline next iteration's loads over this
    // iteration's FMAs (no rolled-loop back-edge serialization).
    #pragma unroll
    for (int a = 0; a < KH; a++) {
        // conflict-free window: 8 floats per channel as two aligned LDS.128
        float win[C_IN][8];
        #pragma unroll
        for (int c = 0; c < C_IN; c++) {
            const float4 lo = *(const float4*)&sx[c][a][w0];
            const float4 hi = *(const float4*)&sx[c][a][w0 + 4];
            win[c][0] = lo.x; win[c][1] = lo.y; win[c][2] = lo.z; win[c][3] = lo.w;
            win[c][4] = hi.x; win[c][5] = hi.y; win[c][6] = hi.z; win[c][7] = hi.w;
        }

        const float4* fa = fp + (size_t)(a * KW) * (UPSQ * THW / 4);

        #pragma unroll
        for (int b = 0; b < KW; b++) {
            const float4* fk = fa + (size_t)b * (UPSQ * THW / 4);
            float4 fv[UG];
            #pragma unroll
            for (int j = 0; j < UG; j++)
                fv[j] = __ldg(fk + (size_t)j * (THW / 4));

            #pragma unroll
            for (int c = 0; c < C_IN; c++) {
                const float p0 = win[c][b];
                const float p1 = win[c][b + 1];
                const float p2 = win[c][b + 2];
                const float p3 = win[c][b + 3];
                #pragma unroll
                for (int j = 0; j < UG; j++) {
                    acc[c][j].x = fmaf(p0, fv[j].x, acc[c][j].x);
                    acc[c][j].y = fmaf(p1, fv[j].y, acc[c][j].y);
                    acc[c][j].z = fmaf(p2, fv[j].z, acc[c][j].z);
                    acc[c][j].w = fmaf(p3, fv[j].w, acc[c][j].w);
                }
            }
        }
    }

    // out[(c*16 + u0 + j)*THW + rowbase + w0], 512B/warp streaming stores
    float4* op = (float4*)(out + (size_t)u0 * THW + rowbase + w0);
    #pragma unroll
    for (int c = 0; c < C_IN; c++)
        #pragma unroll
        for (int j = 0; j < UG; j++)
            __stcs(&op[((size_t)c * UPSQ + j) * (THW / 4)], acc[c][j]);
}

extern "C" void kernel_launch(void* const* d_in, const int* in_sizes, int n_in,
                              void* d_out, int out_size)
{
    const float* x = (const float*)d_in[0];
    const float* f = (const float*)d_in[1];
    float* out = (float*)d_out;

    dim3 grid(T_DIM * H_DIM, 2);  // (t*h row, u-half)
    dim3 block(128);
    duf_kernel<<<grid, block>>>(x, f, out);
}

// round 9
// speedup vs baseline: 1.0386x; 1.0045x over previous
#include <cuda_runtime.h>

// DynamicUpsamplingFilter:
//   x:       (1, 3, 25, 128, 128) float32          -> d_in[0]
//   filters: (1, 25, 16, 25, 128, 128) float32     -> d_in[1]
//   out:     (1, 48, 25, 128, 128) float32
// out[c*16+u, t, h, w] = sum_{a,b} x[c, t, h+a-2, w+b-2] * filters[a*5+b, u, t, h, w]
//
// R9: R8 (UG=2, 7 CTAs/SM, full a-unroll, float4 LDG, conflict-free LDS,
// __stcs stores) +
//  - __ldcs on the one-touch filter stream (evict-first L2 allocation)
//  - grid = (2, 3200): u-half pairs of the same row are adjacent in launch
//    order -> co-resident -> x rows hit L2 for the second block.

#define T_DIM 25
#define H_DIM 128
#define W_DIM 128
#define HW    (H_DIM * W_DIM)       // 16384
#define THW   (T_DIM * HW)          // 409600
#define C_IN  3
#define KH    5
#define KW    5
#define UPSQ  16
#define UG    2                     // u per thread

__global__ __launch_bounds__(128, 7)
void duf_kernel(const float* __restrict__ x,
                const float* __restrict__ f,
                float* __restrict__ out)
{
    const int tid = threadIdx.x;
    const int w4  = tid & 31;            // float4 index over w
    const int ug  = tid >> 5;            // 0..3
    const int w0  = w4 << 2;
    const int h = blockIdx.y & (H_DIM - 1);
    const int t = blockIdx.y >> 7;
    const int u0 = blockIdx.x * 8 + ug * UG;   // first u of this thread

    // x patch tile: 3 channels x 5 rows x (128 + 4) cols, zero halo in w.
    __shared__ __align__(16) float sx[C_IN][KH][W_DIM + 4];

    if (tid < 2) {
        #pragma unroll
        for (int c = 0; c < C_IN; c++)
            #pragma unroll
            for (int a = 0; a < KH; a++) {
                sx[c][a][tid] = 0.0f;
                sx[c][a][W_DIM + 2 + tid] = 0.0f;
            }
    }

    // stage x rows h-2..h+2 for all 3 channels (tid = w index here)
    #pragma unroll
    for (int c = 0; c < C_IN; c++) {
        #pragma unroll
        for (int a = 0; a < KH; a++) {
            const int hh = h + a - 2;
            float v = 0.0f;
            if (hh >= 0 && hh < H_DIM)
                v = __ldg(&x[c * THW + t * HW + hh * W_DIM + tid]);
            sx[c][a][tid + 2] = v;
        }
    }
    __syncthreads();

    const int rowbase = t * HW + h * W_DIM;
    // filter pointer for (k=0, u=u0, this row, w0)
    const float4* fp = (const float4*)(f + (size_t)u0 * THW + rowbase + w0);

    float4 acc[C_IN][UG];
    #pragma unroll
    for (int c = 0; c < C_IN; c++)
        #pragma unroll
        for (int j = 0; j < UG; j++)
            acc[c][j] = make_float4(0.f, 0.f, 0.f, 0.f);

    // FULL unroll: ptxas pipelines next iteration's loads over this
    // iteration's FMAs.
    #pragma unroll
    for (int a = 0; a < KH; a++) {
        // conflict-free window: 8 floats per channel as two aligned LDS.128
        float win[C_IN][8];
        #pragma unroll
        for (int c = 0; c < C_IN; c++) {
            const float4 lo = *(const float4*)&sx[c][a][w0];
            const float4 hi = *(const float4*)&sx[c][a][w0 + 4];
            win[c][0] = lo.x; win[c][1] = lo.y; win[c][2] = lo.z; win[c][3] = lo.w;
            win[c][4] = hi.x; win[c][5] = hi.y; win[c][6] = hi.z; win[c][7] = hi.w;
        }

        const float4* fa = fp + (size_t)(a * KW) * (UPSQ * THW / 4);

        #pragma unroll
        for (int b = 0; b < KW; b++) {
            const float4* fk = fa + (size_t)b * (UPSQ * THW / 4);
            float4 fv[UG];
            #pragma unroll
            for (int j = 0; j < UG; j++)
                fv[j] = __ldcs(fk + (size_t)j * (THW / 4));

            #pragma unroll
            for (int c = 0; c < C_IN; c++) {
                const float p0 = win[c][b];
                const float p1 = win[c][b + 1];
                const float p2 = win[c][b + 2];
                const float p3 = win[c][b + 3];
                #pragma unroll
                for (int j = 0; j < UG; j++) {
                    acc[c][j].x = fmaf(p0, fv[j].x, acc[c][j].x);
                    acc[c][j].y = fmaf(p1, fv[j].y, acc[c][j].y);
                    acc[c][j].z = fmaf(p2, fv[j].z, acc[c][j].z);
                    acc[c][j].w = fmaf(p3, fv[j].w, acc[c][j].w);
                }
            }
        }
    }

    // out[(c*16 + u0 + j)*THW + rowbase + w0], 512B/warp streaming stores
    float4* op = (float4*)(out + (size_t)u0 * THW + rowbase + w0);
    #pragma unroll
    for (int c = 0; c < C_IN; c++)
        #pragma unroll
        for (int j = 0; j < UG; j++)
            __stcs(&op[((size_t)c * UPSQ + j) * (THW / 4)], acc[c][j]);
}

extern "C" void kernel_launch(void* const* d_in, const int* in_sizes, int n_in,
                              void* d_out, int out_size)
{
    const float* x = (const float*)d_in[0];
    const float* f = (const float*)d_in[1];
    float* out = (float*)d_out;

    dim3 grid(2, T_DIM * H_DIM);  // (u-half, t*h row): pairs adjacent in launch order
    dim3 block(128);
    duf_kernel<<<grid, block>>>(x, f, out);
}